// round 11
// baseline (speedup 1.0000x reference)
#include <cuda_runtime.h>
#include <math.h>
#include <stdint.h>

#define N_FFT       512
#define N_BINS      257
#define N_FILT      128
#define OUT_SZ      262144
#define N_T         128

// ---------------- device scratch (no allocations allowed) ----------------
__device__ double       g_cos[N_FFT];
__device__ double       g_sin[N_FFT];
__device__ float        g_mag[N_BINS];
__device__ float        g_adapted[N_FILT];
__device__ float        g_activity[OUT_SZ];
__device__ unsigned int g_min_u;     // ordered-uint encoded float min
__device__ unsigned int g_max_u;     // ordered-uint encoded float max
__device__ unsigned int g_done = 0;  // last-block-done counter (self-resetting)

// monotonic float <-> uint mapping so atomicMin/Max on uint == float min/max
__device__ __forceinline__ unsigned int f2ord(float f) {
    unsigned int u = __float_as_uint(f);
    return (u & 0x80000000u) ? ~u : (u | 0x80000000u);
}
__device__ __forceinline__ float ord2f(unsigned int u) {
    return __uint_as_float((u & 0x80000000u) ? (u ^ 0x80000000u) : ~u);
}

// 16-byte cp.async, L2-only (.cg) — streaming W, no L1 pollution
__device__ __forceinline__ void cp_async16(void* smem_dst, const void* gmem_src) {
    unsigned int s;
    asm("{ .reg .u64 t; cvta.to.shared.u64 t, %1; cvt.u32.u64 %0, t; }"
        : "=r"(s) : "l"(smem_dst));
    asm volatile("cp.async.cg.shared.global [%0], [%1], 16;\n"
                 :: "r"(s), "l"(gmem_src) : "memory");
}

// ---------------- kernel T: twiddle table ----------------
// 512 sincospi total, one per thread (vs 131k inline calls in the DFT loop,
// which profiled at 29.3us of pure latency stall). Values identical to the
// inline-sincospi version -> g_mag bit-identical (verified R5: rel_err=0).
__global__ void kT_twiddle() {
    const int i = threadIdx.x + blockIdx.x * 256;   // 0..511
    double s, c;
    sincospi(-(double)i / 256.0, &s, &c);
    g_cos[i] = c;
    g_sin[i] = s;
}

// ---------------- kernel AB: DFT magnitude + (last block) mel/haircell ----------------
// 257 blocks x 128 threads. Each block computes one bin's fp64 DFT magnitude
// using the twiddle table (8 DFMA + table loads per thread). The LAST block
// to finish additionally runs the mel filterbank + hair cell stage (strict
// in-order fp32 FMA chain per filter) and initializes the min/max atomics.
// The done-counter self-resets so the kernel is graph-replay deterministic.
__global__ void __launch_bounds__(128)
kAB(const float* __restrict__ audio, const float* __restrict__ fb,
    const float* __restrict__ adapt) {
    const int k   = blockIdx.x;     // 0..256
    const int tid = threadIdx.x;    // 128 threads
    double re = 0.0, im = 0.0;
    for (int j = tid; j < N_FFT; j += 128) {
        double x = (double)audio[j];
        int idx = (k * j) & (N_FFT - 1);           // (k*j) mod 512
        re += x * g_cos[idx];
        im += x * g_sin[idx];
    }
    __shared__ double sre[128], sim[128];
    __shared__ int s_last;
    sre[tid] = re; sim[tid] = im;
    __syncthreads();
    for (int off = 64; off > 0; off >>= 1) {
        if (tid < off) { sre[tid] += sre[tid + off]; sim[tid] += sim[tid + off]; }
        __syncthreads();
    }
    if (tid == 0) {
        double r = sre[0], i = sim[0];
        g_mag[k] = (float)sqrt(r * r + i * i);
        __threadfence();                               // publish g_mag[k]
        s_last = (atomicAdd(&g_done, 1u) == N_BINS - 1);
    }
    __syncthreads();
    if (!s_last) return;

    // ---- last block: mel + haircell (thread-per-filter) ----
    if (tid == 0) g_done = 0;                          // reset for next replay
    __threadfence();                                   // acquire: all g_mag visible
    __shared__ float s_mag[N_BINS];
    for (int j = tid; j < N_BINS; j += 128) s_mag[j] = g_mag[j];
    __syncthreads();

    const float* row = fb + (size_t)tid * N_BINS;
    float acc = 0.0f;
    for (int j = 0; j < N_BINS; j++)
        acc = __fmaf_rn(row[j], s_mag[j], acc);        // strict sequential order

    float base = __fadd_rn(acc, 1e-6f);
    float hair = (float)pow((double)base, (double)0.3f);
    float sup  = __fmul_rn(adapt[tid], 0.5f);
    g_adapted[tid] = fmaxf(0.0f, __fsub_rn(hair, sup));

    if (tid == 0) { g_min_u = 0xFFFFFFFFu; g_max_u = 0u; }
}

// ------------- kernel C: activity = W @ adapted + b, with min/max -------------
// 256 rows per CTA. W staged through smem in 8 k-chunks of 16 B/row via a
// TRIPLE-buffered cp.async pipeline (one barrier per chunk). Coalesced 16B
// ops, XOR-swizzled layout. Per-row arithmetic: strict in-order fp32 FMA
// chain over k=0..127 -> bit-identical to the Eigen/XLA reference.
__global__ void __launch_bounds__(256)
kC_gemv(const float4* __restrict__ W4, const float* __restrict__ b) {
    __shared__ float4 s_ad[32];
    __shared__ float4 tile[3][256 * 4];       // 3 x 16 KB
    __shared__ unsigned int s_min, s_max;
    const int tid  = threadIdx.x;
    const int row0 = blockIdx.x * 256;        // 1024 CTAs * 256 rows == OUT_SZ

    if (tid < 32) s_ad[tid] = ((const float4*)g_adapted)[tid];
    if (tid == 0) { s_min = 0xFFFFFFFFu; s_max = 0u; }

#define SWZ(row, i) ((i) ^ (((row) ^ ((row) >> 2)) & 3))
#define STAGE(c) {                                                           \
        const int _buf = (c) % 3;                                            \
        _Pragma("unroll")                                                    \
        for (int u = 0; u < 4; u++) {                                        \
            int l   = u * 256 + tid;                                         \
            int row = l >> 2;                                                \
            int i   = l & 3;                                                 \
            cp_async16(&tile[_buf][row * 4 + SWZ(row, i)],                   \
                       &W4[(size_t)(row0 + row) * 32 + (c) * 4 + i]);        \
        }                                                                    \
        asm volatile("cp.async.commit_group;\n" ::: "memory"); }

    STAGE(0); STAGE(1);

    float acc = 0.0f;
#pragma unroll
    for (int c = 0; c < 8; c++) {
        if (c < 7) asm volatile("cp.async.wait_group 1;\n" ::: "memory");
        else       asm volatile("cp.async.wait_group 0;\n" ::: "memory");
        __syncthreads();
        // stage chunk c+2: its buffer was consumed at iter c-1, retired by
        // the barrier above -> safe; loads overlap this chunk's compute
        if (c < 6) STAGE(c + 2);
        const float4* buf = tile[c % 3];
#pragma unroll
        for (int i = 0; i < 4; i++) {
            float4 w = buf[tid * 4 + SWZ(tid, i)];
            float4 a = s_ad[c * 4 + i];
            acc = __fmaf_rn(w.x, a.x, acc);
            acc = __fmaf_rn(w.y, a.y, acc);
            acc = __fmaf_rn(w.z, a.z, acc);
            acc = __fmaf_rn(w.w, a.w, acc);
        }
    }
#undef STAGE
#undef SWZ

    const int r = row0 + tid;
    float act = __fadd_rn(acc, b[r]);
    g_activity[r] = act;

    // min/max reduce (ordered-uint; min/max order-invariant => exact)
    unsigned int o  = f2ord(act);
    unsigned int mn = o, mx = o;
#pragma unroll
    for (int off = 16; off > 0; off >>= 1) {
        mn = min(mn, __shfl_xor_sync(0xFFFFFFFFu, mn, off));
        mx = max(mx, __shfl_xor_sync(0xFFFFFFFFu, mx, off));
    }
    if ((tid & 31) == 0) { atomicMin(&s_min, mn); atomicMax(&s_max, mx); }
    __syncthreads();
    if (tid == 0) { atomicMin(&g_min_u, s_min); atomicMax(&g_max_u, s_max); }
}

// ------------- kernel E: latency coding -> dense float32 spike raster -------------
// Output float32 [128, 262144]. 2D grid: x covers neuron quads, y covers
// 8-timestep chunks. Streams constant ZERO float4s for the whole chunk
// (doubles as zero-fill, no per-t compares), then overwrites the single
// spike element with a scalar 1.0f store (same thread, program order ->
// later store wins). Exact reference fp32 op order for latency/fire.
#define T_CHUNK 8
__global__ void __launch_bounds__(256)
kE_spikes(float* __restrict__ out) {
    const int q  = blockIdx.x * 256 + threadIdx.x;  // quad index: 0..65535
    const int t0 = blockIdx.y * T_CHUNK;
    const float amin = ord2f(g_min_u);
    const float amax = ord2f(g_max_u);
    const float denom = __fadd_rn(__fsub_rn(amax, amin), 1e-6f);

    const float4 a = ((const float4*)g_activity)[q];
    int   lat[4];
    bool  fire[4];
    {
        float av[4] = {a.x, a.y, a.z, a.w};
#pragma unroll
        for (int i = 0; i < 4; i++) {
            float norm = __fdiv_rn(__fsub_rn(av[i], amin), denom);
            float latf = __fmul_rn(__fsub_rn(1.0f, norm), 127.0f);
            lat[i]  = (int)latf;              // trunc toward zero == astype(int32)
            fire[i] = (norm > 0.05f);
        }
    }

    float4* dst = (float4*)out + q;           // row stride OUT_SZ/4 float4s
    const float4 z4 = make_float4(0.f, 0.f, 0.f, 0.f);
#pragma unroll
    for (int t = t0; t < t0 + T_CHUNK; t++)
        dst[(size_t)t * (OUT_SZ / 4)] = z4;

#pragma unroll
    for (int i = 0; i < 4; i++) {
        if (fire[i] && lat[i] >= t0 && lat[i] < t0 + T_CHUNK)
            out[(size_t)lat[i] * OUT_SZ + 4 * q + i] = 1.0f;
    }
}

// ---------------- launch ----------------
extern "C" void kernel_launch(void* const* d_in, const int* in_sizes, int n_in,
                              void* d_out, int out_size) {
    const float* audio = (const float*)d_in[0];   // [16000]
    const float* fb    = (const float*)d_in[1];   // [128, 257]
    const float* W     = (const float*)d_in[2];   // [262144, 128]
    const float* b     = (const float*)d_in[3];   // [262144]
    const float* adapt = (const float*)d_in[4];   // [128]
    (void)in_sizes; (void)n_in; (void)out_size;

    kT_twiddle<<<2, 256>>>();
    kAB     <<<N_BINS, 128>>>(audio, fb, adapt);
    kC_gemv <<<OUT_SZ / 256, 256>>>((const float4*)W, b);
    dim3 gE(OUT_SZ / 4 / 256, N_T / T_CHUNK);     // (256, 16)
    kE_spikes<<<gE, 256>>>((float*)d_out);
}

// round 12
// speedup vs baseline: 1.0093x; 1.0093x over previous
#include <cuda_runtime.h>
#include <math.h>
#include <stdint.h>

#define N_FFT       512
#define N_BINS      257
#define N_FILT      128
#define OUT_SZ      262144
#define N_T         128

// ---------------- device scratch (no allocations allowed) ----------------
__device__ double       g_cos[N_FFT];
__device__ double       g_sin[N_FFT];
__device__ float        g_mag[N_BINS];
__device__ float        g_adapted[N_FILT];
__device__ float        g_activity[OUT_SZ];
__device__ unsigned int g_min_u;     // ordered-uint encoded float min
__device__ unsigned int g_max_u;     // ordered-uint encoded float max
__device__ unsigned int g_done = 0;  // last-block-done counter (self-resetting)

// monotonic float <-> uint mapping so atomicMin/Max on uint == float min/max
__device__ __forceinline__ unsigned int f2ord(float f) {
    unsigned int u = __float_as_uint(f);
    return (u & 0x80000000u) ? ~u : (u | 0x80000000u);
}
__device__ __forceinline__ float ord2f(unsigned int u) {
    return __uint_as_float((u & 0x80000000u) ? (u ^ 0x80000000u) : ~u);
}

// 16-byte cp.async, L2-only (.cg) — streaming W, no L1 pollution
__device__ __forceinline__ void cp_async16(void* smem_dst, const void* gmem_src) {
    unsigned int s;
    asm("{ .reg .u64 t; cvta.to.shared.u64 t, %1; cvt.u32.u64 %0, t; }"
        : "=r"(s) : "l"(smem_dst));
    asm volatile("cp.async.cg.shared.global [%0], [%1], 16;\n"
                 :: "r"(s), "l"(gmem_src) : "memory");
}

// ---------------- kernel T: twiddle table ----------------
// 512 sincospi total, one per thread (vs 131k inline calls in the DFT loop,
// which profiled at 29.3us of pure latency stall). Values identical to the
// inline-sincospi version -> g_mag bit-identical (verified R5: rel_err=0).
__global__ void kT_twiddle() {
    const int i = threadIdx.x + blockIdx.x * 256;   // 0..511
    double s, c;
    sincospi(-(double)i / 256.0, &s, &c);
    g_cos[i] = c;
    g_sin[i] = s;
}

// ---------------- kernel AB: DFT magnitude + (last block) mel/haircell ----------------
// 257 blocks x 128 threads. Each block computes one bin's fp64 DFT magnitude
// using the twiddle table (8 DFMA + table loads per thread). The LAST block
// to finish additionally runs the mel filterbank + hair cell stage (strict
// in-order fp32 FMA chain per filter) and initializes the min/max atomics.
// The done-counter self-resets so the kernel is graph-replay deterministic.
__global__ void __launch_bounds__(128)
kAB(const float* __restrict__ audio, const float* __restrict__ fb,
    const float* __restrict__ adapt) {
    const int k   = blockIdx.x;     // 0..256
    const int tid = threadIdx.x;    // 128 threads
    double re = 0.0, im = 0.0;
    for (int j = tid; j < N_FFT; j += 128) {
        double x = (double)audio[j];
        int idx = (k * j) & (N_FFT - 1);           // (k*j) mod 512
        re += x * g_cos[idx];
        im += x * g_sin[idx];
    }
    __shared__ double sre[128], sim[128];
    __shared__ int s_last;
    sre[tid] = re; sim[tid] = im;
    __syncthreads();
    for (int off = 64; off > 0; off >>= 1) {
        if (tid < off) { sre[tid] += sre[tid + off]; sim[tid] += sim[tid + off]; }
        __syncthreads();
    }
    if (tid == 0) {
        double r = sre[0], i = sim[0];
        g_mag[k] = (float)sqrt(r * r + i * i);
        __threadfence();                               // publish g_mag[k]
        s_last = (atomicAdd(&g_done, 1u) == N_BINS - 1);
    }
    __syncthreads();
    if (!s_last) return;

    // ---- last block: mel + haircell (thread-per-filter) ----
    if (tid == 0) g_done = 0;                          // reset for next replay
    __threadfence();                                   // acquire: all g_mag visible
    __shared__ float s_mag[N_BINS];
    for (int j = tid; j < N_BINS; j += 128) s_mag[j] = g_mag[j];
    __syncthreads();

    const float* row = fb + (size_t)tid * N_BINS;
    float acc = 0.0f;
    for (int j = 0; j < N_BINS; j++)
        acc = __fmaf_rn(row[j], s_mag[j], acc);        // strict sequential order

    float base = __fadd_rn(acc, 1e-6f);
    float hair = (float)pow((double)base, (double)0.3f);
    float sup  = __fmul_rn(adapt[tid], 0.5f);
    g_adapted[tid] = fmaxf(0.0f, __fsub_rn(hair, sup));

    if (tid == 0) { g_min_u = 0xFFFFFFFFu; g_max_u = 0u; }
}

// ------------- kernel C: activity = W @ adapted + b, with min/max -------------
// 256 rows per CTA. W staged through smem in 8 k-chunks of 16 B/row via a
// TRIPLE-buffered cp.async pipeline (one barrier per chunk). Coalesced 16B
// ops, XOR-swizzled layout. Per-row arithmetic: strict in-order fp32 FMA
// chain over k=0..127 -> bit-identical to the Eigen/XLA reference.
__global__ void __launch_bounds__(256)
kC_gemv(const float4* __restrict__ W4, const float* __restrict__ b) {
    __shared__ float4 s_ad[32];
    __shared__ float4 tile[3][256 * 4];       // 3 x 16 KB
    __shared__ unsigned int s_min, s_max;
    const int tid  = threadIdx.x;
    const int row0 = blockIdx.x * 256;        // 1024 CTAs * 256 rows == OUT_SZ

    if (tid < 32) s_ad[tid] = ((const float4*)g_adapted)[tid];
    if (tid == 0) { s_min = 0xFFFFFFFFu; s_max = 0u; }

#define SWZ(row, i) ((i) ^ (((row) ^ ((row) >> 2)) & 3))
#define STAGE(c) {                                                           \
        const int _buf = (c) % 3;                                            \
        _Pragma("unroll")                                                    \
        for (int u = 0; u < 4; u++) {                                        \
            int l   = u * 256 + tid;                                         \
            int row = l >> 2;                                                \
            int i   = l & 3;                                                 \
            cp_async16(&tile[_buf][row * 4 + SWZ(row, i)],                   \
                       &W4[(size_t)(row0 + row) * 32 + (c) * 4 + i]);        \
        }                                                                    \
        asm volatile("cp.async.commit_group;\n" ::: "memory"); }

    STAGE(0); STAGE(1);

    float acc = 0.0f;
#pragma unroll
    for (int c = 0; c < 8; c++) {
        if (c < 7) asm volatile("cp.async.wait_group 1;\n" ::: "memory");
        else       asm volatile("cp.async.wait_group 0;\n" ::: "memory");
        __syncthreads();
        // stage chunk c+2: its buffer was consumed at iter c-1, retired by
        // the barrier above -> safe; loads overlap this chunk's compute
        if (c < 6) STAGE(c + 2);
        const float4* buf = tile[c % 3];
#pragma unroll
        for (int i = 0; i < 4; i++) {
            float4 w = buf[tid * 4 + SWZ(tid, i)];
            float4 a = s_ad[c * 4 + i];
            acc = __fmaf_rn(w.x, a.x, acc);
            acc = __fmaf_rn(w.y, a.y, acc);
            acc = __fmaf_rn(w.z, a.z, acc);
            acc = __fmaf_rn(w.w, a.w, acc);
        }
    }
#undef STAGE
#undef SWZ

    const int r = row0 + tid;
    float act = __fadd_rn(acc, b[r]);
    g_activity[r] = act;

    // min/max reduce (ordered-uint; min/max order-invariant => exact)
    unsigned int o  = f2ord(act);
    unsigned int mn = o, mx = o;
#pragma unroll
    for (int off = 16; off > 0; off >>= 1) {
        mn = min(mn, __shfl_xor_sync(0xFFFFFFFFu, mn, off));
        mx = max(mx, __shfl_xor_sync(0xFFFFFFFFu, mx, off));
    }
    if ((tid & 31) == 0) { atomicMin(&s_min, mn); atomicMax(&s_max, mx); }
    __syncthreads();
    if (tid == 0) { atomicMin(&g_min_u, s_min); atomicMax(&g_max_u, s_max); }
}

// ------------- kernel E: latency coding -> dense float32 spike raster -------------
// Output float32 [128, 262144]. 2D grid: x covers neuron quads, y covers
// 8-timestep chunks. Streams constant ZERO float4s for the whole chunk
// (doubles as zero-fill, no per-t compares), then overwrites the single
// spike element with a scalar 1.0f store (same thread, program order ->
// later store wins). Exact reference fp32 op order for latency/fire.
#define T_CHUNK 8
__global__ void __launch_bounds__(256)
kE_spikes(float* __restrict__ out) {
    const int q  = blockIdx.x * 256 + threadIdx.x;  // quad index: 0..65535
    const int t0 = blockIdx.y * T_CHUNK;
    const float amin = ord2f(g_min_u);
    const float amax = ord2f(g_max_u);
    const float denom = __fadd_rn(__fsub_rn(amax, amin), 1e-6f);

    const float4 a = ((const float4*)g_activity)[q];
    int   lat[4];
    bool  fire[4];
    {
        float av[4] = {a.x, a.y, a.z, a.w};
#pragma unroll
        for (int i = 0; i < 4; i++) {
            float norm = __fdiv_rn(__fsub_rn(av[i], amin), denom);
            float latf = __fmul_rn(__fsub_rn(1.0f, norm), 127.0f);
            lat[i]  = (int)latf;              // trunc toward zero == astype(int32)
            fire[i] = (norm > 0.05f);
        }
    }

    float4* dst = (float4*)out + q;           // row stride OUT_SZ/4 float4s
    const float4 z4 = make_float4(0.f, 0.f, 0.f, 0.f);
#pragma unroll
    for (int t = t0; t < t0 + T_CHUNK; t++)
        dst[(size_t)t * (OUT_SZ / 4)] = z4;

#pragma unroll
    for (int i = 0; i < 4; i++) {
        if (fire[i] && lat[i] >= t0 && lat[i] < t0 + T_CHUNK)
            out[(size_t)lat[i] * OUT_SZ + 4 * q + i] = 1.0f;
    }
}

// ---------------- launch ----------------
extern "C" void kernel_launch(void* const* d_in, const int* in_sizes, int n_in,
                              void* d_out, int out_size) {
    const float* audio = (const float*)d_in[0];   // [16000]
    const float* fb    = (const float*)d_in[1];   // [128, 257]
    const float* W     = (const float*)d_in[2];   // [262144, 128]
    const float* b     = (const float*)d_in[3];   // [262144]
    const float* adapt = (const float*)d_in[4];   // [128]
    (void)in_sizes; (void)n_in; (void)out_size;

    kT_twiddle<<<2, 256>>>();
    kAB     <<<N_BINS, 128>>>(audio, fb, adapt);
    kC_gemv <<<OUT_SZ / 256, 256>>>((const float4*)W, b);
    dim3 gE(OUT_SZ / 4 / 256, N_T / T_CHUNK);     // (256, 16)
    kE_spikes<<<gE, 256>>>((float*)d_out);
}